// round 16
// baseline (speedup 1.0000x reference)
#include <cuda_runtime.h>
#include <cuda_fp16.h>
#include <math.h>
#include <stdint.h>

#define NB 64
#define NN 2048
#define NC 64
#define ND 10
#define NJ 4096          // NB*NC
#define KI 192           // cheb_k * C_IN

// ------------------ scratch (static device globals) ------------------
__device__ __half g_S   [NN * NN];            // fp16 supports
__device__ __half g_Xq  [(size_t)NJ * NN];    // [j][m] fp16
__device__ __half g_Y1h [(size_t)NN * NJ];    // [n][j] fp16
__device__ __half g_Y2h [(size_t)NN * NJ];    // [n][j] fp16
__device__ __half g_W16 [(size_t)NN * KI * NC];  // [n][ki][o] fp16

// ------------------ helpers ------------------
__device__ __forceinline__ uint32_t smem_u32(const void* p) {
    uint32_t a;
    asm("{ .reg .u64 t; cvta.to.shared.u64 t, %1; cvt.u32.u64 %0, t; }" : "=r"(a) : "l"(p));
    return a;
}
__device__ __forceinline__ void cpa16(uint32_t s, const void* g) {
    asm volatile("cp.async.cg.shared.global [%0], [%1], 16;" :: "r"(s), "l"(g));
}

#define LDSM4(r, a) \
    asm volatile("ldmatrix.sync.aligned.m8n8.x4.shared.b16 {%0,%1,%2,%3}, [%4];" \
        : "=r"((r)[0]), "=r"((r)[1]), "=r"((r)[2]), "=r"((r)[3]) : "r"(a))

#define LDSM4T(r, a) \
    asm volatile("ldmatrix.sync.aligned.m8n8.x4.trans.shared.b16 {%0,%1,%2,%3}, [%4];" \
        : "=r"((r)[0]), "=r"((r)[1]), "=r"((r)[2]), "=r"((r)[3]) : "r"(a))

#define MMA_F16(c, a, b0, b1) \
    asm volatile("mma.sync.aligned.m16n8k16.row.col.f32.f16.f16.f32 " \
        "{%0,%1,%2,%3}, {%4,%5,%6,%7}, {%8,%9}, {%0,%1,%2,%3};" \
        : "+f"((c)[0]), "+f"((c)[1]), "+f"((c)[2]), "+f"((c)[3]) \
        : "r"((a)[0]), "r"((a)[1]), "r"((a)[2]), "r"((a)[3]), "r"(b0), "r"(b1))

// ============================================================
// prep_sx: supports + Xq (what the GEMMs need), interleaved 1:2
// ============================================================
#define PSX_TOTAL 6144   // 2048 supports + 4096 xq

__global__ __launch_bounds__(256) void prep_sx_kernel(const float* __restrict__ x,
                                                      const float* __restrict__ E) {
    __shared__ float sh[2048 + 256];
    const int tid = threadIdx.x;
    const int bid = blockIdx.x;
    const int r3 = bid % 3;
    const int q3 = bid / 3;    // 0..2047

    if (r3 == 0) {
        // ---- supports row n (no max-subtraction: relu bounds exp input) ----
        float* vals = sh;
        float* red  = sh + 2048;
        const int n = q3;

        float en[ND];
#pragma unroll
        for (int d = 0; d < ND; d++) en[d] = E[n * ND + d];

        float lsum = 0.f;
        for (int m = tid; m < NN; m += 256) {
            float v = 0.f;
#pragma unroll
            for (int d = 0; d < ND; d++) v = fmaf(en[d], E[m * ND + d], v);
            float e = __expf(fmaxf(v, 0.f));
            vals[m] = e;
            lsum += e;
        }
        red[tid] = lsum; __syncthreads();
        for (int s = 128; s > 0; s >>= 1) { if (tid < s) red[tid] += red[tid + s]; __syncthreads(); }
        const float inv = 1.f / red[0];
        for (int m = tid; m < NN; m += 256)
            g_S[n * NN + m] = __float2half_rn(vals[m] * inv);

    } else {
        // ---- Xq tile: Xq[b*64+c][m] = fp16(x[b][m][c]) ----
        const int id = q3 * 2 + (r3 - 1);    // 0..4095
        const int m0 = (id & 63) * 32;
        const int b  = id >> 6;
        float* sm = sh;   // 64*33 floats
#pragma unroll
        for (int p = 0; p < 8; p++) {
            int e = tid + 256 * p;
            int rr = e >> 6, c = e & 63;
            sm[c * 33 + rr] = x[(size_t)b * (NN * NC) + (size_t)(m0 + rr) * NC + c];
        }
        __syncthreads();
#pragma unroll
        for (int p = 0; p < 4; p++) {
            int e = tid + 256 * p;
            int c = e >> 4, r2 = (e & 15) * 2;
            __half2 hp = __floats2half2_rn(sm[c * 33 + r2], sm[c * 33 + r2 + 1]);
            *(__half2*)&g_Xq[(size_t)(b * 64 + c) * NN + m0 + r2] = hp;
        }
    }
}

// ============================================================
// prep_w: W16[n, e] = fp16(sum_d E[n,d]*Wp[d,e]) — side stream,
// overlaps the DRAM-idle GEMMs; joined before output kernel.
// ============================================================
__global__ __launch_bounds__(256) void prep_w_kernel(const float* __restrict__ E,
                                                     const float* __restrict__ Wp) {
    __shared__ float Es[16 * ND];
    const int tid = threadIdx.x;
    const int id = blockIdx.x;           // 0..6143
    const int e0 = (id % 48) * 256;
    const int n0 = (id / 48) * 16;
    if (tid < 16 * ND) Es[tid] = E[(n0 + tid / ND) * ND + (tid % ND)];
    __syncthreads();
    const int e = e0 + tid;
    float wp[ND];
#pragma unroll
    for (int d = 0; d < ND; d++) wp[d] = Wp[d * (KI * NC) + e];
#pragma unroll
    for (int nn = 0; nn < 16; nn++) {
        float acc = 0.f;
#pragma unroll
        for (int d = 0; d < ND; d++) acc = fmaf(Es[nn * ND + d], wp[d], acc);
        g_W16[(size_t)(n0 + nn) * (KI * NC) + e] = __float2half_rn(acc);
    }
}

// ============================================================
// single-term fp16 GEMM (m16n8k16): C[128x128] tile, 256 threads,
// 8 warps (2x4), warp tile 64x32. 3-stage cp.async, 2 CTAs/SM.
// MODE 1: B = Xq [j][m] k-major, out = Y1h [n][j]
// MODE 2: B = Y1h [m][j] mn-major (ldmatrix.trans), out = Y2h
// ============================================================
#define STG_A 0
#define STG_B 16384
#define STAGE_BYTES 32768
#define GEMM_SMEM 98304
#define NITER (NN / 64)            // 32

template <int MODE>
__global__ void __launch_bounds__(256, 2) gemm_fp16_kernel() {
    extern __shared__ float dsm[];
    const int t = threadIdx.x;
    const int l = t & 31;
    const int wid = t >> 5;
    const int wm = wid >> 2;
    const int wn = wid & 3;
    const int bm = blockIdx.y * 128;
    const int bn = blockIdx.x * 128;

    const __half* Ap = g_S + (size_t)bm * NN;

    const uint32_t sb0 = smem_u32(dsm);

    auto load_stage = [&](int s, int k0) {
        const uint32_t sb = sb0 + (uint32_t)s * STAGE_BYTES;
#pragma unroll
        for (int p = 0; p < 4; p++) {
            const int g = t + 256 * p;
            const int row = g >> 3;
            const int c16 = g & 7;
            const int sw = c16 ^ (row & 7);
            cpa16(sb + STG_A + (uint32_t)(row * 128 + sw * 16),
                  Ap + (size_t)row * NN + k0 + c16 * 8);
        }
        if (MODE == 1) {
            const __half* Bp = g_Xq + (size_t)bn * NN;
#pragma unroll
            for (int p = 0; p < 4; p++) {
                const int g = t + 256 * p;
                const int row = g >> 3;
                const int c16 = g & 7;
                const int sw = c16 ^ (row & 7);
                cpa16(sb + STG_B + (uint32_t)(row * 128 + sw * 16),
                      Bp + (size_t)row * NN + k0 + c16 * 8);
            }
        } else {
#pragma unroll
            for (int p = 0; p < 4; p++) {
                const int g = t + 256 * p;
                const int k = g >> 4;
                const int jg = g & 15;
                const uint32_t dst = (uint32_t)(k * 256 + ((jg >> 3) << 7) +
                                                (((jg & 7) ^ (k & 7)) << 4));
                cpa16(sb + STG_B + dst,
                      g_Y1h + (size_t)(k0 + k) * NJ + bn + jg * 8);
            }
        }
        asm volatile("cp.async.commit_group;" ::: "memory");
    };

    float acc[4][4][4];
#pragma unroll
    for (int a = 0; a < 4; a++)
#pragma unroll
        for (int b = 0; b < 4; b++)
#pragma unroll
            for (int c = 0; c < 4; c++) acc[a][b][c] = 0.f;

    const int t4 = l >> 3;
    const int l7 = l & 7;
    const int arow_in = ((t4 & 1) << 3) + l7;
    const int brow_in = ((t4 >> 1) << 3) + l7;
    const uint32_t abase = (uint32_t)((wm * 64 + arow_in) * 128);
    const uint32_t bbase = (uint32_t)((wn * 32 + brow_in) * 128);
    const int akg = t4 >> 1;
    const int bkg = t4 & 1;
    const int b2row_in = ((t4 & 1) << 3) + l7;
    const int b2gsel   = t4 >> 1;

    load_stage(0, 0);
    load_stage(1, 64);

    for (int i = 0; i < NITER; i++) {
        if (i + 2 < NITER)
            asm volatile("cp.async.wait_group 1;" ::: "memory");
        else
            asm volatile("cp.async.wait_group 0;" ::: "memory");
        __syncthreads();
        if (i + 2 < NITER) load_stage((i + 2) % 3, (i + 2) * 64);
        const uint32_t sb = sb0 + (uint32_t)(i % 3) * STAGE_BYTES;
#pragma unroll
        for (int ks = 0; ks < 4; ks++) {
            const uint32_t xa = (uint32_t)(((ks * 2 + akg) ^ l7) << 4);
            uint32_t af[4][4], bf[2][4];
#pragma unroll
            for (int mt = 0; mt < 4; mt++)
                LDSM4(af[mt], sb + STG_A + abase + (uint32_t)(mt * 16 * 128) + xa);
            if (MODE == 1) {
                const uint32_t xb = (uint32_t)(((ks * 2 + bkg) ^ l7) << 4);
#pragma unroll
                for (int nh = 0; nh < 2; nh++)
                    LDSM4(bf[nh], sb + STG_B + bbase + (uint32_t)(nh * 16 * 128) + xb);
            } else {
#pragma unroll
                for (int nh = 0; nh < 2; nh++) {
                    const int kr = ks * 16 + b2row_in;
                    const int jg = wn * 4 + nh * 2 + b2gsel;
                    const uint32_t addr = (uint32_t)(kr * 256 + ((jg >> 3) << 7) +
                                                     (((jg & 7) ^ (kr & 7)) << 4));
                    LDSM4T(bf[nh], sb + STG_B + addr);
                }
            }
#pragma unroll
            for (int mt = 0; mt < 4; mt++)
#pragma unroll
                for (int n8 = 0; n8 < 4; n8++) {
                    const int nh = n8 >> 1, q = (n8 & 1) * 2;
                    MMA_F16(acc[mt][n8], af[mt], bf[nh][q], bf[nh][q + 1]);
                }
        }
    }

    // ---------------- epilogue: Y fp16 [n][j] ----------------
    __half* Yh = (MODE == 1) ? g_Y1h : g_Y2h;
    const int lm = l >> 2;
    const int lc = (l & 3) << 1;
#pragma unroll
    for (int mt = 0; mt < 4; mt++)
#pragma unroll
        for (int n8 = 0; n8 < 4; n8++) {
            const int r = bm + wm * 64 + mt * 16 + lm;
            const int col = bn + wn * 32 + n8 * 8 + lc;
            *(__half2*)&Yh[(size_t)r * NJ + col] =
                __floats2half2_rn(acc[mt][n8][0], acc[mt][n8][1]);
            *(__half2*)&Yh[(size_t)(r + 8) * NJ + col] =
                __floats2half2_rn(acc[mt][n8][2], acc[mt][n8][3]);
        }
}

// ============================================================
// output (tensor-core, single-term): out[b,o] = A[b,ki]@W[ki,o] + bias
// ============================================================
#define OUT_SMEM 49152   // AHI 24576 + WHI 24576

__global__ void __launch_bounds__(256, 3) output_kernel(const float* __restrict__ x,
                                                        const float* __restrict__ E,
                                                        const float* __restrict__ bp,
                                                        float* __restrict__ out) {
    extern __shared__ char osm[];
    const uint32_t base = smem_u32(osm);
    const uint32_t AHI = base;
    const uint32_t WHI = base + 24576;

    const int n = blockIdx.x;
    const int tid = threadIdx.x;
    const int l = tid & 31;
    const int wid = tid >> 5;
    const int wm = wid >> 2;
    const int wn = wid & 3;

    const __half* Whg = g_W16 + (size_t)n * (KI * NC);
#pragma unroll
    for (int p = 0; p < 6; p++) {
        const int g = tid + 256 * p;
        const int ki = g >> 3;
        const int og = g & 7;
        cpa16(WHI + (uint32_t)(ki * 128 + ((og ^ (ki & 7)) << 4)),
              Whg + ki * 64 + og * 8);
    }
    asm volatile("cp.async.commit_group;" ::: "memory");

#pragma unroll
    for (int it = 0; it < 8; it++) {
        const int e = tid * 2 + it * 512;
        const int b = e >> 6;
        const int i = e & 63;
        const float2 xv = *(const float2*)&x[(size_t)b * (NN * NC) + n * NC + i];
        const float2 y1 = __half22float2(*(const __half2*)&g_Y1h[(size_t)n * NJ + e]);
        const float2 y2 = __half22float2(*(const __half2*)&g_Y2h[(size_t)n * NJ + e]);
        const float2 vals[3] = { xv, y1,
            make_float2(2.f * y2.x - xv.x, 2.f * y2.y - xv.y) };
#pragma unroll
        for (int kch = 0; kch < 3; kch++) {
            const int ki = kch * 64 + i;
            const uint32_t addr = (uint32_t)(b * 384 + ((ki >> 6) << 7) +
                ((((ki >> 3) & 7) ^ (b & 7)) << 4) + ((ki & 7) << 1));
            *(__half2*)(osm + addr) = __floats2half2_rn(vals[kch].x, vals[kch].y);
        }
    }
    asm volatile("cp.async.wait_group 0;" ::: "memory");
    __syncthreads();

    float acc[2][2][4];
#pragma unroll
    for (int a = 0; a < 2; a++)
#pragma unroll
        for (int b = 0; b < 2; b++)
#pragma unroll
            for (int c = 0; c < 4; c++) acc[a][b][c] = 0.f;

    const int t4 = l >> 3;
    const int l7 = l & 7;
    const int arow_in = ((t4 & 1) << 3) + l7;
    const int akg = t4 >> 1;
    const int wrow_in = ((t4 & 1) << 3) + l7;
    const int wog = wn * 2 + (t4 >> 1);

#pragma unroll
    for (int ks = 0; ks < 12; ks++) {
        uint32_t ahf[2][4], whf[4];
        const int kg = ks * 2 + akg;
#pragma unroll
        for (int mt = 0; mt < 2; mt++) {
            const int row = wm * 32 + mt * 16 + arow_in;
            const uint32_t aaddr = (uint32_t)(row * 384 + ((kg >> 3) << 7) +
                (((kg & 7) ^ (row & 7)) << 4));
            LDSM4(ahf[mt], AHI + aaddr);
        }
        {
            const int wrow = ks * 16 + wrow_in;
            LDSM4T(whf, WHI + (uint32_t)(wrow * 128 + ((wog ^ (wrow & 7)) << 4)));
        }
#pragma unroll
        for (int mt = 0; mt < 2; mt++)
#pragma unroll
            for (int n8 = 0; n8 < 2; n8++)
                MMA_F16(acc[mt][n8], ahf[mt], whf[n8 * 2], whf[n8 * 2 + 1]);
    }

    const int lm = l >> 2;
    const int lc = (l & 3) << 1;
    float bias[2][2];
#pragma unroll
    for (int n8 = 0; n8 < 2; n8++)
#pragma unroll
        for (int cc = 0; cc < 2; cc++) {
            const int o = wn * 16 + n8 * 8 + lc + cc;
            float s = 0.f;
#pragma unroll
            for (int d = 0; d < ND; d++) s = fmaf(E[n * ND + d], bp[d * NC + o], s);
            bias[n8][cc] = s;
        }

#pragma unroll
    for (int mt = 0; mt < 2; mt++)
#pragma unroll
        for (int n8 = 0; n8 < 2; n8++) {
            const int b0 = wm * 32 + mt * 16 + lm;
            const int col = wn * 16 + n8 * 8 + lc;
            *(float2*)&out[(size_t)b0 * (NN * NC) + n * NC + col] =
                make_float2(acc[mt][n8][0] + bias[n8][0], acc[mt][n8][1] + bias[n8][1]);
            *(float2*)&out[(size_t)(b0 + 8) * (NN * NC) + n * NC + col] =
                make_float2(acc[mt][n8][2] + bias[n8][0], acc[mt][n8][3] + bias[n8][1]);
        }
}

// ============================================================
extern "C" void kernel_launch(void* const* d_in, const int* in_sizes, int n_in,
                              void* d_out, int out_size) {
    (void)in_sizes; (void)n_in; (void)out_size;
    const float* x  = (const float*)d_in[0];
    const float* E  = (const float*)d_in[1];
    const float* Wp = (const float*)d_in[2];
    const float* bp = (const float*)d_in[3];
    float* out = (float*)d_out;

    cudaFuncSetAttribute(output_kernel, cudaFuncAttributeMaxDynamicSharedMemorySize, OUT_SMEM);
    cudaFuncSetAttribute(gemm_fp16_kernel<1>, cudaFuncAttributeMaxDynamicSharedMemorySize, GEMM_SMEM);
    cudaFuncSetAttribute(gemm_fp16_kernel<2>, cudaFuncAttributeMaxDynamicSharedMemorySize, GEMM_SMEM);

    // fork weights prep onto a side stream (no device allocation involved)
    cudaStream_t sw;
    cudaEvent_t e_fork, e_join;
    cudaStreamCreateWithFlags(&sw, cudaStreamNonBlocking);
    cudaEventCreateWithFlags(&e_fork, cudaEventDisableTiming);
    cudaEventCreateWithFlags(&e_join, cudaEventDisableTiming);

    cudaEventRecord(e_fork, 0);
    cudaStreamWaitEvent(sw, e_fork, 0);
    prep_w_kernel<<<6144, 256, 0, sw>>>(E, Wp);   // overlaps GEMMs
    cudaEventRecord(e_join, sw);

    prep_sx_kernel<<<PSX_TOTAL, 256>>>(x, E);

    dim3 ggrid(NJ / 128, NN / 128);   // (32, 16) = 512 CTAs
    gemm_fp16_kernel<1><<<ggrid, 256, GEMM_SMEM>>>();
    gemm_fp16_kernel<2><<<ggrid, 256, GEMM_SMEM>>>();

    cudaStreamWaitEvent(0, e_join, 0);
    output_kernel<<<NN, 256, OUT_SMEM>>>(x, E, bp, out);
}